// round 2
// baseline (speedup 1.0000x reference)
#include <cuda_runtime.h>
#include <cstddef>

// Problem constants
#define Bn 4
#define Sn 2048
#define En 100
#define Fn 64
#define Cn 8922

// Scratch (device globals; no allocation allowed)
__device__ float g_h[4 * Bn * Sn * Fn];      // [branch][b][s][f], 8.4MB
__device__ float g_part[16 * Cn];            // [branch][b][c] partial Wf-dots
__device__ float g_lsum[256];                // per-block loss partials

// ---------------- packed f32x2 helpers ----------------
__device__ __forceinline__ void fma2(unsigned long long& d, unsigned long long a,
                                     unsigned long long b) {
    asm("fma.rn.f32x2 %0, %1, %2, %0;" : "+l"(d) : "l"(a), "l"(b));
}
__device__ __forceinline__ unsigned long long pack2(float x, float y) {
    unsigned long long r;
    asm("mov.b64 %0, {%1, %2};" : "=l"(r) : "f"(x), "f"(y));
    return r;
}
__device__ __forceinline__ float2 unpack2(unsigned long long v) {
    float2 r;
    asm("mov.b64 {%0, %1}, %2;" : "=f"(r.x), "=f"(r.y) : "l"(v));
    return r;
}

// ---------------- conv + tanh -> h ----------------
// Block: 256 threads, computes a [64 s x 64 f] tile for one (b, branch).
// smem: xe tile [72 rows x 104 cols] + w chunk [20e x K taps x 68(pad) f]
template <int K>
__device__ void conv_body(const int* __restrict__ x, const float* __restrict__ embed,
                          const float* __restrict__ w, const float* __restrict__ bias,
                          float* __restrict__ hout, int b, int s0, float* sm) {
    float* xe = sm;                // 72*104 floats
    float* ws = sm + 72 * 104;    // 20*K*68 floats
    const int tid = threadIdx.x;

    // load embedding tile (rows s0-4 .. s0+67), zero-padded outside [0,S)
    for (int i = tid; i < 72 * 26; i += 256) {
        int row = i / 26, q = i - row * 26;
        int s = s0 - 4 + row;
        float4 v = make_float4(0.f, 0.f, 0.f, 0.f);
        if (q < 25 && s >= 0 && s < Sn) {
            v = ((const float4*)(embed + (size_t)x[b * Sn + s] * En))[q];
        }
        ((float4*)(xe + row * 104))[q] = v;
    }

    const int tx = tid & 15, ty = tid >> 4;
    float acc[4][4];
#pragma unroll
    for (int i = 0; i < 4; i++)
#pragma unroll
        for (int j = 0; j < 4; j++) acc[i][j] = 0.f;

    const int ROW_OFF = 4 - K / 2;

    for (int ec = 0; ec < 5; ec++) {
        __syncthreads();
        // load w chunk: gmem layout [f][e][t] (coalesced read), smem [e][t][f+pad]
        for (int i = tid; i < 64 * 20 * K; i += 256) {
            int f = i / (20 * K);
            int r = i - f * (20 * K);
            int e = r / K, t = r - e * K;
            ws[(e * K + t) * 68 + f] = w[(size_t)f * En * K + (size_t)(ec * 20 + e) * K + t];
        }
        __syncthreads();

        for (int e = 0; e < 20; e++) {
#pragma unroll
            for (int t = 0; t < K; t++) {
                float4 wv = *((const float4*)(ws + (e * K + t) * 68 + tx * 4));
                float xs[4];
#pragma unroll
                for (int i = 0; i < 4; i++)
                    xs[i] = xe[(ty * 4 + i + t + ROW_OFF) * 104 + ec * 20 + e];
#pragma unroll
                for (int i = 0; i < 4; i++) {
                    acc[i][0] = fmaf(xs[i], wv.x, acc[i][0]);
                    acc[i][1] = fmaf(xs[i], wv.y, acc[i][1]);
                    acc[i][2] = fmaf(xs[i], wv.z, acc[i][2]);
                    acc[i][3] = fmaf(xs[i], wv.w, acc[i][3]);
                }
            }
        }
    }

    float b0 = bias[tx * 4 + 0], b1 = bias[tx * 4 + 1];
    float b2 = bias[tx * 4 + 2], b3 = bias[tx * 4 + 3];
#pragma unroll
    for (int i = 0; i < 4; i++) {
        int s = s0 + ty * 4 + i;
        float4 o;
        o.x = tanhf(acc[i][0] + b0);
        o.y = tanhf(acc[i][1] + b1);
        o.z = tanhf(acc[i][2] + b2);
        o.w = tanhf(acc[i][3] + b3);
        *((float4*)(hout + ((size_t)b * Sn + s) * Fn + tx * 4)) = o;
    }
}

__global__ __launch_bounds__(256) void conv_kernel(
    const int* __restrict__ x, const float* __restrict__ embed,
    const float* __restrict__ w3, const float* __restrict__ b3,
    const float* __restrict__ w5, const float* __restrict__ b5,
    const float* __restrict__ w7, const float* __restrict__ b7,
    const float* __restrict__ w9, const float* __restrict__ b9) {
    extern __shared__ float sm[];
    int s0 = blockIdx.x * 64;
    int b = blockIdx.y;
    int branch = blockIdx.z;
    float* hout = g_h + (size_t)branch * Bn * Sn * Fn;
    switch (branch) {
        case 0: conv_body<3>(x, embed, w3, b3, hout, b, s0, sm); break;
        case 1: conv_body<5>(x, embed, w5, b5, hout, b, s0, sm); break;
        case 2: conv_body<7>(x, embed, w7, b7, hout, b, s0, sm); break;
        case 3: conv_body<9>(x, embed, w9, b9, hout, b, s0, sm); break;
    }
}

// ---------------- fused attention pooling ----------------
// One thread per output class c; block of 128 threads shares h-tiles in smem.
// No max-subtraction in softmax: |score| << 1 by construction.
__global__ __launch_bounds__(128) void attn_kernel(
    const float* __restrict__ U0, const float* __restrict__ U1,
    const float* __restrict__ U2, const float* __restrict__ U3,
    const float* __restrict__ Wf) {
    const int branch = blockIdx.y;
    const int b = blockIdx.z;
    const int c = blockIdx.x * 128 + threadIdx.x;
    const int cc = c < Cn ? c : Cn - 1;
    const float* U = (branch == 0) ? U0 : (branch == 1) ? U1 : (branch == 2) ? U2 : U3;
    const float* hp = g_h + ((size_t)(branch * Bn + b)) * Sn * Fn;

    __shared__ float hs[64 * 64];

    unsigned long long u2[32], m2[32];
    {
        const ulonglong2* up = (const ulonglong2*)(U + (size_t)cc * Fn);
#pragma unroll
        for (int j = 0; j < 16; j++) {
            ulonglong2 v = up[j];
            u2[2 * j] = v.x;
            u2[2 * j + 1] = v.y;
        }
    }
#pragma unroll
    for (int j = 0; j < 32; j++) m2[j] = 0ull;
    float D = 0.f;

    for (int s0 = 0; s0 < Sn; s0 += 64) {
        __syncthreads();
        {
            const float4* src = (const float4*)(hp + (size_t)s0 * Fn);
            float4* dst = (float4*)hs;
#pragma unroll
            for (int j = 0; j < 8; j++) dst[threadIdx.x + 128 * j] = src[threadIdx.x + 128 * j];
        }
        __syncthreads();

        for (int s = 0; s < 64; s++) {
            const ulonglong2* hr = (const ulonglong2*)(hs + s * 64);
            unsigned long long a0 = 0, a1 = 0, a2 = 0, a3 = 0;
#pragma unroll
            for (int j = 0; j < 16; j += 2) {
                ulonglong2 h0 = hr[j];
                ulonglong2 h1 = hr[j + 1];
                fma2(a0, u2[2 * j], h0.x);
                fma2(a1, u2[2 * j + 1], h0.y);
                fma2(a2, u2[2 * j + 2], h1.x);
                fma2(a3, u2[2 * j + 3], h1.y);
            }
            float2 f0 = unpack2(a0), f1 = unpack2(a1), f2 = unpack2(a2), f3 = unpack2(a3);
            float score = ((f0.x + f0.y) + (f1.x + f1.y)) + ((f2.x + f2.y) + (f3.x + f3.y));
            float p = __expf(score);
            D += p;
            unsigned long long pp = pack2(p, p);
#pragma unroll
            for (int j = 0; j < 16; j++) {
                ulonglong2 hv = hr[j];
                fma2(m2[2 * j], pp, hv.x);
                fma2(m2[2 * j + 1], pp, hv.y);
            }
        }
    }

    if (c < Cn) {
        const float* wfp = Wf + (size_t)c * (4 * Fn) + branch * Fn;
        float acc = 0.f;
#pragma unroll
        for (int j = 0; j < 32; j++) {
            float2 mv = unpack2(m2[j]);
            acc = fmaf(mv.x, wfp[2 * j], acc);
            acc = fmaf(mv.y, wfp[2 * j + 1], acc);
        }
        g_part[((size_t)branch * Bn + b) * Cn + c] = acc / D;
    }
}

// ---------------- y_hat + per-block loss partials ----------------
__global__ __launch_bounds__(256) void yhat_kernel(const float* __restrict__ y,
                                                   const float* __restrict__ bf,
                                                   float* __restrict__ out) {
    int i = blockIdx.x * 256 + threadIdx.x;
    float lt = 0.f;
    if (i < Bn * Cn) {
        int b = i / Cn, c = i - b * Cn;
        float yh = bf[c];
#pragma unroll
        for (int br = 0; br < 4; br++) yh += g_part[((size_t)br * Bn + b) * Cn + c];
        out[i] = yh;
        lt = fmaxf(yh, 0.f) - yh * y[i] + log1pf(expf(-fabsf(yh)));
    }
    __shared__ float red[256];
    red[threadIdx.x] = lt;
    __syncthreads();
    for (int o = 128; o > 0; o >>= 1) {
        if (threadIdx.x < o) red[threadIdx.x] += red[threadIdx.x + o];
        __syncthreads();
    }
    if (threadIdx.x == 0) g_lsum[blockIdx.x] = red[0];
}

__global__ void loss_kernel(float* __restrict__ out, int pos, int nblocks) {
    __shared__ float red[256];
    float s = 0.f;
    for (int i = threadIdx.x; i < nblocks; i += 256) s += g_lsum[i];
    red[threadIdx.x] = s;
    __syncthreads();
    for (int o = 128; o > 0; o >>= 1) {
        if (threadIdx.x < o) red[threadIdx.x] += red[threadIdx.x + o];
        __syncthreads();
    }
    if (threadIdx.x == 0) out[pos] = red[0] / (float)(Bn * Cn);
}

// ---------------- launch ----------------
extern "C" void kernel_launch(void* const* d_in, const int* in_sizes, int n_in,
                              void* d_out, int out_size) {
    const int* x = (const int*)d_in[0];
    const float* y = (const float*)d_in[1];
    const float* embed = (const float*)d_in[2];
    const float* w3 = (const float*)d_in[3];
    const float* b3 = (const float*)d_in[4];
    const float* w5 = (const float*)d_in[5];
    const float* b5 = (const float*)d_in[6];
    const float* w7 = (const float*)d_in[7];
    const float* b7 = (const float*)d_in[8];
    const float* w9 = (const float*)d_in[9];
    const float* b9 = (const float*)d_in[10];
    const float* U3 = (const float*)d_in[11];
    const float* U5 = (const float*)d_in[12];
    const float* U7 = (const float*)d_in[13];
    const float* U9 = (const float*)d_in[14];
    const float* Wf = (const float*)d_in[15];
    const float* bf = (const float*)d_in[16];
    float* out = (float*)d_out;

    const int CONV_SMEM = (72 * 104 + 20 * 9 * 68) * 4;  // 78912 B
    cudaFuncSetAttribute(conv_kernel, cudaFuncAttributeMaxDynamicSharedMemorySize, CONV_SMEM);

    conv_kernel<<<dim3(Sn / 64, Bn, 4), 256, CONV_SMEM>>>(x, embed, w3, b3, w5, b5, w7, b7, w9, b9);

    attn_kernel<<<dim3((Cn + 127) / 128, 4, Bn), 128>>>(U3, U5, U7, U9, Wf);

    const int nblocks = (Bn * Cn + 255) / 256;  // 140
    yhat_kernel<<<nblocks, 256>>>(y, bf, out);

    if (out_size > Bn * Cn) {
        loss_kernel<<<1, 256>>>(out, out_size - 1, nblocks);
    }
}

// round 4
// speedup vs baseline: 5.2013x; 5.2013x over previous
#include <cuda_runtime.h>
#include <cuda_bf16.h>
#include <cstdint>
#include <cstddef>

#define Bn 4
#define Sn 2048
#define En 100
#define Fn 64
#define Cn 8922
#define CT 128
#define STL 128
#define NT (Sn / STL)
#define NCT ((Cn + CT - 1) / CT)
#define SPAD 72  // padded bf16 row stride in smem (conflict-free B-frag loads)

// ---------------- device scratch (no allocs allowed) ----------------
__device__ __nv_bfloat16 g_hb[4 * Bn * Sn * Fn];  // [br][b][s][f]
__device__ float g_hsum[16 * Fn];                  // fp32 col sums of h
__device__ __nv_bfloat16 g_Ub[4 * Cn * Fn];
__device__ __nv_bfloat16 g_Wb[4 * Cn * Fn];
__device__ float g_q[16 * Cn];
__device__ float g_Ds[16 * Cn];
__device__ float g_lsum[256];

// ---------------- packed f32x2 helpers ----------------
__device__ __forceinline__ unsigned long long pack2(float x, float y) {
    unsigned long long r;
    asm("mov.b64 %0, {%1, %2};" : "=l"(r) : "f"(x), "f"(y));
    return r;
}
__device__ __forceinline__ float2 unpack2(unsigned long long v) {
    float2 r;
    asm("mov.b64 {%0, %1}, %2;" : "=f"(r.x), "=f"(r.y) : "l"(v));
    return r;
}
__device__ __forceinline__ unsigned long long fma2(unsigned long long a, unsigned long long b,
                                                   unsigned long long c) {
    unsigned long long d;
    asm("fma.rn.f32x2 %0, %1, %2, %3;" : "=l"(d) : "l"(a), "l"(b), "l"(c));
    return d;
}
__device__ __forceinline__ unsigned long long mul2(unsigned long long a, unsigned long long b) {
    unsigned long long d;
    asm("mul.rn.f32x2 %0, %1, %2;" : "=l"(d) : "l"(a), "l"(b));
    return d;
}
__device__ __forceinline__ unsigned long long add2(unsigned long long a, unsigned long long b) {
    unsigned long long d;
    asm("add.rn.f32x2 %0, %1, %2;" : "=l"(d) : "l"(a), "l"(b));
    return d;
}

// warp-level bf16 MMA: D(16x8,f32) += A(16x16,bf16,row) * B(16x8,bf16,col)
__device__ __forceinline__ void mma16816(float d[4], const uint32_t a[4], const uint32_t b[2]) {
    asm volatile(
        "mma.sync.aligned.m16n8k16.row.col.f32.bf16.bf16.f32 "
        "{%0,%1,%2,%3}, {%4,%5,%6,%7}, {%8,%9}, {%0,%1,%2,%3};"
        : "+f"(d[0]), "+f"(d[1]), "+f"(d[2]), "+f"(d[3])
        : "r"(a[0]), "r"(a[1]), "r"(a[2]), "r"(a[3]), "r"(b[0]), "r"(b[1]));
}

// ---------------- prep: bf16 U/Wf, zero hsum ----------------
__global__ __launch_bounds__(256) void prep_kernel(const float* __restrict__ U3,
                                                   const float* __restrict__ U5,
                                                   const float* __restrict__ U7,
                                                   const float* __restrict__ U9,
                                                   const float* __restrict__ Wf) {
    int j = blockIdx.x * 256 + threadIdx.x;
    if (j < 16 * Fn) g_hsum[j] = 0.f;
    if (j >= 4 * Cn * Fn) return;
    int br = j / (Cn * Fn);
    int r = j - br * (Cn * Fn);
    int c = r / Fn, f = r - c * Fn;
    const float* U = br == 0 ? U3 : br == 1 ? U5 : br == 2 ? U7 : U9;
    g_Ub[j] = __float2bfloat16(U[r]);
    g_Wb[j] = __float2bfloat16(Wf[(size_t)c * (4 * Fn) + br * Fn + f]);
}

// ---------------- conv + tanh -> bf16 h + fp32 hsum ----------------
template <int K>
__device__ void conv_body(const int* __restrict__ x, const float* __restrict__ embed,
                          const float* __restrict__ w, const float* __restrict__ bias,
                          __nv_bfloat16* __restrict__ hout, float* __restrict__ hsum,
                          int b, int s0, float* sm) {
    float* xe = sm;
    float* ws = sm + 72 * 104;
    const int tid = threadIdx.x;

    for (int i = tid; i < 72 * 26; i += 256) {
        int row = i / 26, q = i - row * 26;
        int s = s0 - 4 + row;
        float4 v = make_float4(0.f, 0.f, 0.f, 0.f);
        if (q < 25 && s >= 0 && s < Sn)
            v = ((const float4*)(embed + (size_t)x[b * Sn + s] * En))[q];
        ((float4*)(xe + row * 104))[q] = v;
    }

    const int tx = tid & 15, ty = tid >> 4;
    float acc[4][4];
#pragma unroll
    for (int i = 0; i < 4; i++)
#pragma unroll
        for (int j = 0; j < 4; j++) acc[i][j] = 0.f;

    const int ROW_OFF = 4 - K / 2;

    for (int ec = 0; ec < 5; ec++) {
        __syncthreads();
        for (int i = tid; i < 64 * 20 * K; i += 256) {
            int f = i / (20 * K);
            int r = i - f * (20 * K);
            int e = r / K, t = r - e * K;
            ws[(e * K + t) * 68 + f] = w[(size_t)f * En * K + (size_t)(ec * 20 + e) * K + t];
        }
        __syncthreads();

        for (int e = 0; e < 20; e++) {
#pragma unroll
            for (int t = 0; t < K; t++) {
                float4 wv = *((const float4*)(ws + (e * K + t) * 68 + tx * 4));
                float xs[4];
#pragma unroll
                for (int i = 0; i < 4; i++)
                    xs[i] = xe[(ty * 4 + i + t + ROW_OFF) * 104 + ec * 20 + e];
#pragma unroll
                for (int i = 0; i < 4; i++) {
                    acc[i][0] = fmaf(xs[i], wv.x, acc[i][0]);
                    acc[i][1] = fmaf(xs[i], wv.y, acc[i][1]);
                    acc[i][2] = fmaf(xs[i], wv.z, acc[i][2]);
                    acc[i][3] = fmaf(xs[i], wv.w, acc[i][3]);
                }
            }
        }
    }

    float b0 = bias[tx * 4 + 0], b1 = bias[tx * 4 + 1];
    float b2 = bias[tx * 4 + 2], b3 = bias[tx * 4 + 3];
    float ts0 = 0.f, ts1 = 0.f, ts2 = 0.f, ts3 = 0.f;
#pragma unroll
    for (int i = 0; i < 4; i++) {
        int s = s0 + ty * 4 + i;
        float t0 = tanhf(acc[i][0] + b0);
        float t1 = tanhf(acc[i][1] + b1);
        float t2 = tanhf(acc[i][2] + b2);
        float t3 = tanhf(acc[i][3] + b3);
        ts0 += t0; ts1 += t1; ts2 += t2; ts3 += t3;
        __nv_bfloat162 p01 = __floats2bfloat162_rn(t0, t1);
        __nv_bfloat162 p23 = __floats2bfloat162_rn(t2, t3);
        uint2 pk;
        pk.x = *reinterpret_cast<uint32_t*>(&p01);
        pk.y = *reinterpret_cast<uint32_t*>(&p23);
        *reinterpret_cast<uint2*>(hout + ((size_t)b * Sn + s) * Fn + tx * 4) = pk;
    }

    __syncthreads();
    sm[ty * 64 + tx * 4 + 0] = ts0;
    sm[ty * 64 + tx * 4 + 1] = ts1;
    sm[ty * 64 + tx * 4 + 2] = ts2;
    sm[ty * 64 + tx * 4 + 3] = ts3;
    __syncthreads();
    if (tid < 64) {
        float s = 0.f;
#pragma unroll
        for (int t = 0; t < 16; t++) s += sm[t * 64 + tid];
        atomicAdd(&hsum[tid], s);
    }
}

__global__ __launch_bounds__(256) void conv_kernel(
    const int* __restrict__ x, const float* __restrict__ embed,
    const float* __restrict__ w3, const float* __restrict__ b3,
    const float* __restrict__ w5, const float* __restrict__ b5,
    const float* __restrict__ w7, const float* __restrict__ b7,
    const float* __restrict__ w9, const float* __restrict__ b9) {
    extern __shared__ float sm[];
    int s0 = blockIdx.x * 64;
    int b = blockIdx.y;
    int branch = blockIdx.z;
    __nv_bfloat16* hout = g_hb + (size_t)branch * Bn * Sn * Fn;
    float* hsum = g_hsum + (branch * Bn + b) * Fn;
    switch (branch) {
        case 0: conv_body<3>(x, embed, w3, b3, hout, hsum, b, s0, sm); break;
        case 1: conv_body<5>(x, embed, w5, b5, hout, hsum, b, s0, sm); break;
        case 2: conv_body<7>(x, embed, w7, b7, hout, hsum, b, s0, sm); break;
        case 3: conv_body<9>(x, embed, w9, b9, hout, hsum, b, s0, sm); break;
    }
}

// ---------------- attention via warp-level bf16 mma.sync ----------------
// Block: 256 thr / 8 warps. Tile: 128 c x 128 s. Warp owns 16 c-rows.
// score = U.h^T, g = Wf.h^T computed per 8-col n-tile; delta=expm1(score) poly;
// accumulate q=sum(delta*g), D=sum(delta) per class in registers.
__global__ __launch_bounds__(256) void attn_kernel() {
    __shared__ __align__(16) __nv_bfloat16 hs[STL][SPAD];  // 18 KB

    const int tid = threadIdx.x;
    const int wid = tid >> 5, lane = tid & 31;
    const int ct = blockIdx.x, br = blockIdx.y, b = blockIdx.z;
    const int c0 = ct * CT + wid * 16;

    const int row = lane >> 2;        // 0..7
    const int kq = (lane & 3) * 2;    // 0,2,4,6

    // persistent A fragments (U, Wf) for this warp's 16 c-rows
    uint32_t aU[4][4], aW[4][4];
    {
        const __nv_bfloat16* Ub = g_Ub + (size_t)br * Cn * Fn;
        const __nv_bfloat16* Wb = g_Wb + (size_t)br * Cn * Fn;
        int cA = c0 + row, cB = c0 + row + 8;
        bool vA = cA < Cn, vB = cB < Cn;
#pragma unroll
        for (int ks = 0; ks < 4; ks++) {
            int k = ks * 16 + kq;
            aU[ks][0] = vA ? *(const uint32_t*)(Ub + (size_t)cA * Fn + k) : 0u;
            aU[ks][1] = vB ? *(const uint32_t*)(Ub + (size_t)cB * Fn + k) : 0u;
            aU[ks][2] = vA ? *(const uint32_t*)(Ub + (size_t)cA * Fn + k + 8) : 0u;
            aU[ks][3] = vB ? *(const uint32_t*)(Ub + (size_t)cB * Fn + k + 8) : 0u;
            aW[ks][0] = vA ? *(const uint32_t*)(Wb + (size_t)cA * Fn + k) : 0u;
            aW[ks][1] = vB ? *(const uint32_t*)(Wb + (size_t)cB * Fn + k) : 0u;
            aW[ks][2] = vA ? *(const uint32_t*)(Wb + (size_t)cA * Fn + k + 8) : 0u;
            aW[ks][3] = vB ? *(const uint32_t*)(Wb + (size_t)cB * Fn + k + 8) : 0u;
        }
    }

    const __nv_bfloat16* hsrc = g_hb + (size_t)(br * Bn + b) * Sn * Fn;

    // prefetch tile 0 into registers (4 x uint4 per thread)
    uint4 pf[4];
#pragma unroll
    for (int k = 0; k < 4; k++) {
        int i = tid + 256 * k;
        pf[k] = ((const uint4*)hsrc)[i];
    }

    const unsigned long long C1 = pack2(1.f, 1.f);
    const unsigned long long C2 = pack2(0.5f, 0.5f);
    const unsigned long long C3 = pack2(1.f / 6.f, 1.f / 6.f);
    const unsigned long long C4 = pack2(1.f / 24.f, 1.f / 24.f);
    unsigned long long qacc0 = 0ull, qacc1 = 0ull, dacc0 = 0ull, dacc1 = 0ull;

    for (int st = 0; st < NT; st++) {
        // store prefetched tile to smem (padded rows)
#pragma unroll
        for (int k = 0; k < 4; k++) {
            int i = tid + 256 * k;
            int r = i >> 3, q = i & 7;
            *(uint4*)(&hs[r][q * 8]) = pf[k];
        }
        __syncthreads();

        if (st + 1 < NT) {
            const uint4* nsrc = (const uint4*)(hsrc + (size_t)(st + 1) * STL * Fn);
#pragma unroll
            for (int k = 0; k < 4; k++) pf[k] = nsrc[tid + 256 * k];
        }

#pragma unroll 4
        for (int nt = 0; nt < 16; nt++) {
            const __nv_bfloat16* brow = &hs[nt * 8 + row][0];
            uint32_t bfr[4][2];
#pragma unroll
            for (int ks = 0; ks < 4; ks++) {
                bfr[ks][0] = *(const uint32_t*)(brow + ks * 16 + kq);
                bfr[ks][1] = *(const uint32_t*)(brow + ks * 16 + kq + 8);
            }
            float sD[4] = {0.f, 0.f, 0.f, 0.f};
            float gD[4] = {0.f, 0.f, 0.f, 0.f};
#pragma unroll
            for (int ks = 0; ks < 4; ks++) {
                mma16816(sD, aU[ks], bfr[ks]);
                mma16816(gD, aW[ks], bfr[ks]);
            }
            // epilogue: delta = expm1(score), q += delta*g, D += delta
            unsigned long long x0 = pack2(sD[0], sD[1]);
            unsigned long long x1 = pack2(sD[2], sD[3]);
            unsigned long long g0 = pack2(gD[0], gD[1]);
            unsigned long long g1 = pack2(gD[2], gD[3]);
            unsigned long long t0 = fma2(x0, C4, C3);
            unsigned long long t1 = fma2(x1, C4, C3);
            t0 = fma2(x0, t0, C2);
            t1 = fma2(x1, t1, C2);
            t0 = fma2(x0, t0, C1);
            t1 = fma2(x1, t1, C1);
            unsigned long long dl0 = mul2(x0, t0);
            unsigned long long dl1 = mul2(x1, t1);
            qacc0 = fma2(dl0, g0, qacc0);
            qacc1 = fma2(dl1, g1, qacc1);
            dacc0 = add2(dacc0, dl0);
            dacc1 = add2(dacc1, dl1);
        }
        __syncthreads();
    }

    // horizontal: sum pair, then reduce across the 4 lanes sharing a row
    float2 q0p = unpack2(qacc0), q1p = unpack2(qacc1);
    float2 d0p = unpack2(dacc0), d1p = unpack2(dacc1);
    float q0 = q0p.x + q0p.y, q1 = q1p.x + q1p.y;
    float d0 = d0p.x + d0p.y, d1 = d1p.x + d1p.y;
#pragma unroll
    for (int off = 1; off < 4; off <<= 1) {
        q0 += __shfl_xor_sync(0xFFFFFFFF, q0, off);
        q1 += __shfl_xor_sync(0xFFFFFFFF, q1, off);
        d0 += __shfl_xor_sync(0xFFFFFFFF, d0, off);
        d1 += __shfl_xor_sync(0xFFFFFFFF, d1, off);
    }
    if ((lane & 3) == 0) {
        int base = (br * Bn + b) * Cn;
        int cA = c0 + row, cB = c0 + row + 8;
        if (cA < Cn) { g_q[base + cA] = q0; g_Ds[base + cA] = d0; }
        if (cB < Cn) { g_q[base + cB] = q1; g_Ds[base + cB] = d1; }
    }
}

// ---------------- y_hat + loss ----------------
__global__ __launch_bounds__(256) void yhat_kernel(const float* __restrict__ y,
                                                   const float* __restrict__ Wf,
                                                   const float* __restrict__ bf,
                                                   float* __restrict__ out) {
    int i = blockIdx.x * 256 + threadIdx.x;
    float lt = 0.f;
    if (i < Bn * Cn) {
        int b = i / Cn, c = i - b * Cn;
        float yh = bf[c];
#pragma unroll
        for (int br = 0; br < 4; br++) {
            const float* wfp = Wf + (size_t)c * (4 * Fn) + br * Fn;
            const float* hsv = g_hsum + (br * Bn + b) * Fn;
            float dot = 0.f;
#pragma unroll
            for (int f = 0; f < Fn; f++) dot = fmaf(wfp[f], hsv[f], dot);
            int idx = (br * Bn + b) * Cn + c;
            yh += (dot + g_q[idx]) / (2048.f + g_Ds[idx]);
        }
        out[i] = yh;
        lt = fmaxf(yh, 0.f) - yh * y[i] + log1pf(expf(-fabsf(yh)));
    }
    __shared__ float red[256];
    red[threadIdx.x] = lt;
    __syncthreads();
    for (int o = 128; o > 0; o >>= 1) {
        if (threadIdx.x < o) red[threadIdx.x] += red[threadIdx.x + o];
        __syncthreads();
    }
    if (threadIdx.x == 0) g_lsum[blockIdx.x] = red[0];
}

__global__ void loss_kernel(float* __restrict__ out, int pos, int nblocks) {
    __shared__ float red[256];
    float s = 0.f;
    for (int i = threadIdx.x; i < nblocks; i += 256) s += g_lsum[i];
    red[threadIdx.x] = s;
    __syncthreads();
    for (int o = 128; o > 0; o >>= 1) {
        if (threadIdx.x < o) red[threadIdx.x] += red[threadIdx.x + o];
        __syncthreads();
    }
    if (threadIdx.x == 0) out[pos] = red[0] / (float)(Bn * Cn);
}

// ---------------- launch ----------------
extern "C" void kernel_launch(void* const* d_in, const int* in_sizes, int n_in,
                              void* d_out, int out_size) {
    const int* x = (const int*)d_in[0];
    const float* y = (const float*)d_in[1];
    const float* embed = (const float*)d_in[2];
    const float* w3 = (const float*)d_in[3];
    const float* b3 = (const float*)d_in[4];
    const float* w5 = (const float*)d_in[5];
    const float* b5 = (const float*)d_in[6];
    const float* w7 = (const float*)d_in[7];
    const float* b7 = (const float*)d_in[8];
    const float* w9 = (const float*)d_in[9];
    const float* b9 = (const float*)d_in[10];
    const float* U3 = (const float*)d_in[11];
    const float* U5 = (const float*)d_in[12];
    const float* U7 = (const float*)d_in[13];
    const float* U9 = (const float*)d_in[14];
    const float* Wf = (const float*)d_in[15];
    const float* bf = (const float*)d_in[16];
    float* out = (float*)d_out;

    const int CONV_SMEM = (72 * 104 + 20 * 9 * 68) * 4;
    cudaFuncSetAttribute(conv_kernel, cudaFuncAttributeMaxDynamicSharedMemorySize, CONV_SMEM);

    prep_kernel<<<(4 * Cn * Fn + 255) / 256, 256>>>(U3, U5, U7, U9, Wf);
    conv_kernel<<<dim3(Sn / 64, Bn, 4), 256, CONV_SMEM>>>(x, embed, w3, b3, w5, b5, w7, b7, w9, b9);
    attn_kernel<<<dim3(NCT, 4, Bn), 256>>>();

    const int nblocks = (Bn * Cn + 255) / 256;
    yhat_kernel<<<nblocks, 256>>>(y, Wf, bf, out);
    if (out_size > Bn * Cn) loss_kernel<<<1, 256>>>(out, out_size - 1, nblocks);
}

// round 5
// speedup vs baseline: 5.2140x; 1.0024x over previous
#include <cuda_runtime.h>
#include <cuda_bf16.h>
#include <cstdint>
#include <cstddef>

#define Bn 4
#define Sn 2048
#define En 100
#define Fn 64
#define Cn 8922
#define CT 128
#define STL 128
#define NT (Sn / STL)
#define NCT ((Cn + CT - 1) / CT)
#define SPAD 72  // padded bf16 row stride in smem (conflict-free B-frag loads)

// ---------------- device scratch (no allocs allowed) ----------------
__device__ __nv_bfloat16 g_hb[4 * Bn * Sn * Fn];  // [br][b][s][f]
__device__ float g_hsum[16 * Fn];                  // fp32 col sums of h
__device__ __nv_bfloat16 g_Ub[4 * Cn * Fn];
__device__ __nv_bfloat16 g_Wb[4 * Cn * Fn];
__device__ float g_q[16 * Cn];
__device__ float g_Ds[16 * Cn];
__device__ float g_lsum[256];

// ---------------- packed f32x2 helpers ----------------
__device__ __forceinline__ unsigned long long pack2(float x, float y) {
    unsigned long long r;
    asm("mov.b64 %0, {%1, %2};" : "=l"(r) : "f"(x), "f"(y));
    return r;
}
__device__ __forceinline__ float2 unpack2(unsigned long long v) {
    float2 r;
    asm("mov.b64 {%0, %1}, %2;" : "=f"(r.x), "=f"(r.y) : "l"(v));
    return r;
}
__device__ __forceinline__ unsigned long long fma2(unsigned long long a, unsigned long long b,
                                                   unsigned long long c) {
    unsigned long long d;
    asm("fma.rn.f32x2 %0, %1, %2, %3;" : "=l"(d) : "l"(a), "l"(b), "l"(c));
    return d;
}
__device__ __forceinline__ unsigned long long mul2(unsigned long long a, unsigned long long b) {
    unsigned long long d;
    asm("mul.rn.f32x2 %0, %1, %2;" : "=l"(d) : "l"(a), "l"(b));
    return d;
}
__device__ __forceinline__ unsigned long long add2(unsigned long long a, unsigned long long b) {
    unsigned long long d;
    asm("add.rn.f32x2 %0, %1, %2;" : "=l"(d) : "l"(a), "l"(b));
    return d;
}

// warp-level bf16 MMA: D(16x8,f32) += A(16x16,bf16,row) * B(16x8,bf16,col)
__device__ __forceinline__ void mma16816(float d[4], const uint32_t a[4], const uint32_t b[2]) {
    asm volatile(
        "mma.sync.aligned.m16n8k16.row.col.f32.bf16.bf16.f32 "
        "{%0,%1,%2,%3}, {%4,%5,%6,%7}, {%8,%9}, {%0,%1,%2,%3};"
        : "+f"(d[0]), "+f"(d[1]), "+f"(d[2]), "+f"(d[3])
        : "r"(a[0]), "r"(a[1]), "r"(a[2]), "r"(a[3]), "r"(b[0]), "r"(b[1]));
}

// ---------------- prep: bf16 U/Wf, zero hsum ----------------
__global__ __launch_bounds__(256) void prep_kernel(const float* __restrict__ U3,
                                                   const float* __restrict__ U5,
                                                   const float* __restrict__ U7,
                                                   const float* __restrict__ U9,
                                                   const float* __restrict__ Wf) {
    int j = blockIdx.x * 256 + threadIdx.x;
    if (j < 16 * Fn) g_hsum[j] = 0.f;
    if (j >= 4 * Cn * Fn) return;
    int br = j / (Cn * Fn);
    int r = j - br * (Cn * Fn);
    int c = r / Fn, f = r - c * Fn;
    const float* U = br == 0 ? U3 : br == 1 ? U5 : br == 2 ? U7 : U9;
    g_Ub[j] = __float2bfloat16(U[r]);
    g_Wb[j] = __float2bfloat16(Wf[(size_t)c * (4 * Fn) + br * Fn + f]);
}

// ---------------- conv + tanh -> bf16 h + fp32 hsum ----------------
template <int K>
__device__ void conv_body(const int* __restrict__ x, const float* __restrict__ embed,
                          const float* __restrict__ w, const float* __restrict__ bias,
                          __nv_bfloat16* __restrict__ hout, float* __restrict__ hsum,
                          int b, int s0, float* sm) {
    float* xe = sm;
    float* ws = sm + 72 * 104;
    const int tid = threadIdx.x;

    for (int i = tid; i < 72 * 26; i += 256) {
        int row = i / 26, q = i - row * 26;
        int s = s0 - 4 + row;
        float4 v = make_float4(0.f, 0.f, 0.f, 0.f);
        if (q < 25 && s >= 0 && s < Sn)
            v = ((const float4*)(embed + (size_t)x[b * Sn + s] * En))[q];
        ((float4*)(xe + row * 104))[q] = v;
    }

    const int tx = tid & 15, ty = tid >> 4;
    float acc[4][4];
#pragma unroll
    for (int i = 0; i < 4; i++)
#pragma unroll
        for (int j = 0; j < 4; j++) acc[i][j] = 0.f;

    const int ROW_OFF = 4 - K / 2;

    for (int ec = 0; ec < 5; ec++) {
        __syncthreads();
        for (int i = tid; i < 64 * 20 * K; i += 256) {
            int f = i / (20 * K);
            int r = i - f * (20 * K);
            int e = r / K, t = r - e * K;
            ws[(e * K + t) * 68 + f] = w[(size_t)f * En * K + (size_t)(ec * 20 + e) * K + t];
        }
        __syncthreads();

        for (int e = 0; e < 20; e++) {
#pragma unroll
            for (int t = 0; t < K; t++) {
                float4 wv = *((const float4*)(ws + (e * K + t) * 68 + tx * 4));
                float xs[4];
#pragma unroll
                for (int i = 0; i < 4; i++)
                    xs[i] = xe[(ty * 4 + i + t + ROW_OFF) * 104 + ec * 20 + e];
#pragma unroll
                for (int i = 0; i < 4; i++) {
                    acc[i][0] = fmaf(xs[i], wv.x, acc[i][0]);
                    acc[i][1] = fmaf(xs[i], wv.y, acc[i][1]);
                    acc[i][2] = fmaf(xs[i], wv.z, acc[i][2]);
                    acc[i][3] = fmaf(xs[i], wv.w, acc[i][3]);
                }
            }
        }
    }

    float b0 = bias[tx * 4 + 0], b1 = bias[tx * 4 + 1];
    float b2 = bias[tx * 4 + 2], b3 = bias[tx * 4 + 3];
    float ts0 = 0.f, ts1 = 0.f, ts2 = 0.f, ts3 = 0.f;
#pragma unroll
    for (int i = 0; i < 4; i++) {
        int s = s0 + ty * 4 + i;
        float t0 = tanhf(acc[i][0] + b0);
        float t1 = tanhf(acc[i][1] + b1);
        float t2 = tanhf(acc[i][2] + b2);
        float t3 = tanhf(acc[i][3] + b3);
        ts0 += t0; ts1 += t1; ts2 += t2; ts3 += t3;
        __nv_bfloat162 p01 = __floats2bfloat162_rn(t0, t1);
        __nv_bfloat162 p23 = __floats2bfloat162_rn(t2, t3);
        uint2 pk;
        pk.x = *reinterpret_cast<uint32_t*>(&p01);
        pk.y = *reinterpret_cast<uint32_t*>(&p23);
        *reinterpret_cast<uint2*>(hout + ((size_t)b * Sn + s) * Fn + tx * 4) = pk;
    }

    __syncthreads();
    sm[ty * 64 + tx * 4 + 0] = ts0;
    sm[ty * 64 + tx * 4 + 1] = ts1;
    sm[ty * 64 + tx * 4 + 2] = ts2;
    sm[ty * 64 + tx * 4 + 3] = ts3;
    __syncthreads();
    if (tid < 64) {
        float s = 0.f;
#pragma unroll
        for (int t = 0; t < 16; t++) s += sm[t * 64 + tid];
        atomicAdd(&hsum[tid], s);
    }
}

__global__ __launch_bounds__(256) void conv_kernel(
    const int* __restrict__ x, const float* __restrict__ embed,
    const float* __restrict__ w3, const float* __restrict__ b3,
    const float* __restrict__ w5, const float* __restrict__ b5,
    const float* __restrict__ w7, const float* __restrict__ b7,
    const float* __restrict__ w9, const float* __restrict__ b9) {
    extern __shared__ float sm[];
    int s0 = blockIdx.x * 64;
    int b = blockIdx.y;
    int branch = blockIdx.z;
    __nv_bfloat16* hout = g_hb + (size_t)branch * Bn * Sn * Fn;
    float* hsum = g_hsum + (branch * Bn + b) * Fn;
    switch (branch) {
        case 0: conv_body<3>(x, embed, w3, b3, hout, hsum, b, s0, sm); break;
        case 1: conv_body<5>(x, embed, w5, b5, hout, hsum, b, s0, sm); break;
        case 2: conv_body<7>(x, embed, w7, b7, hout, hsum, b, s0, sm); break;
        case 3: conv_body<9>(x, embed, w9, b9, hout, hsum, b, s0, sm); break;
    }
}

// ---------------- attention via warp-level bf16 mma.sync ----------------
// Block: 256 thr / 8 warps. Tile: 128 c x 128 s. Warp owns 16 c-rows.
// score = U.h^T, g = Wf.h^T computed per 8-col n-tile; delta=expm1(score) poly;
// accumulate q=sum(delta*g), D=sum(delta) per class in registers.
__global__ __launch_bounds__(256) void attn_kernel() {
    __shared__ __align__(16) __nv_bfloat16 hs[STL][SPAD];  // 18 KB

    const int tid = threadIdx.x;
    const int wid = tid >> 5, lane = tid & 31;
    const int ct = blockIdx.x, br = blockIdx.y, b = blockIdx.z;
    const int c0 = ct * CT + wid * 16;

    const int row = lane >> 2;        // 0..7
    const int kq = (lane & 3) * 2;    // 0,2,4,6

    // persistent A fragments (U, Wf) for this warp's 16 c-rows
    uint32_t aU[4][4], aW[4][4];
    {
        const __nv_bfloat16* Ub = g_Ub + (size_t)br * Cn * Fn;
        const __nv_bfloat16* Wb = g_Wb + (size_t)br * Cn * Fn;
        int cA = c0 + row, cB = c0 + row + 8;
        bool vA = cA < Cn, vB = cB < Cn;
#pragma unroll
        for (int ks = 0; ks < 4; ks++) {
            int k = ks * 16 + kq;
            aU[ks][0] = vA ? *(const uint32_t*)(Ub + (size_t)cA * Fn + k) : 0u;
            aU[ks][1] = vB ? *(const uint32_t*)(Ub + (size_t)cB * Fn + k) : 0u;
            aU[ks][2] = vA ? *(const uint32_t*)(Ub + (size_t)cA * Fn + k + 8) : 0u;
            aU[ks][3] = vB ? *(const uint32_t*)(Ub + (size_t)cB * Fn + k + 8) : 0u;
            aW[ks][0] = vA ? *(const uint32_t*)(Wb + (size_t)cA * Fn + k) : 0u;
            aW[ks][1] = vB ? *(const uint32_t*)(Wb + (size_t)cB * Fn + k) : 0u;
            aW[ks][2] = vA ? *(const uint32_t*)(Wb + (size_t)cA * Fn + k + 8) : 0u;
            aW[ks][3] = vB ? *(const uint32_t*)(Wb + (size_t)cB * Fn + k + 8) : 0u;
        }
    }

    const __nv_bfloat16* hsrc = g_hb + (size_t)(br * Bn + b) * Sn * Fn;

    // prefetch tile 0 into registers (4 x uint4 per thread)
    uint4 pf[4];
#pragma unroll
    for (int k = 0; k < 4; k++) {
        int i = tid + 256 * k;
        pf[k] = ((const uint4*)hsrc)[i];
    }

    const unsigned long long C1 = pack2(1.f, 1.f);
    const unsigned long long C2 = pack2(0.5f, 0.5f);
    const unsigned long long C3 = pack2(1.f / 6.f, 1.f / 6.f);
    const unsigned long long C4 = pack2(1.f / 24.f, 1.f / 24.f);
    unsigned long long qacc0 = 0ull, qacc1 = 0ull, dacc0 = 0ull, dacc1 = 0ull;

    for (int st = 0; st < NT; st++) {
        // store prefetched tile to smem (padded rows)
#pragma unroll
        for (int k = 0; k < 4; k++) {
            int i = tid + 256 * k;
            int r = i >> 3, q = i & 7;
            *(uint4*)(&hs[r][q * 8]) = pf[k];
        }
        __syncthreads();

        if (st + 1 < NT) {
            const uint4* nsrc = (const uint4*)(hsrc + (size_t)(st + 1) * STL * Fn);
#pragma unroll
            for (int k = 0; k < 4; k++) pf[k] = nsrc[tid + 256 * k];
        }

#pragma unroll 4
        for (int nt = 0; nt < 16; nt++) {
            const __nv_bfloat16* brow = &hs[nt * 8 + row][0];
            uint32_t bfr[4][2];
#pragma unroll
            for (int ks = 0; ks < 4; ks++) {
                bfr[ks][0] = *(const uint32_t*)(brow + ks * 16 + kq);
                bfr[ks][1] = *(const uint32_t*)(brow + ks * 16 + kq + 8);
            }
            float sD[4] = {0.f, 0.f, 0.f, 0.f};
            float gD[4] = {0.f, 0.f, 0.f, 0.f};
#pragma unroll
            for (int ks = 0; ks < 4; ks++) {
                mma16816(sD, aU[ks], bfr[ks]);
                mma16816(gD, aW[ks], bfr[ks]);
            }
            // epilogue: delta = expm1(score), q += delta*g, D += delta
            unsigned long long x0 = pack2(sD[0], sD[1]);
            unsigned long long x1 = pack2(sD[2], sD[3]);
            unsigned long long g0 = pack2(gD[0], gD[1]);
            unsigned long long g1 = pack2(gD[2], gD[3]);
            unsigned long long t0 = fma2(x0, C4, C3);
            unsigned long long t1 = fma2(x1, C4, C3);
            t0 = fma2(x0, t0, C2);
            t1 = fma2(x1, t1, C2);
            t0 = fma2(x0, t0, C1);
            t1 = fma2(x1, t1, C1);
            unsigned long long dl0 = mul2(x0, t0);
            unsigned long long dl1 = mul2(x1, t1);
            qacc0 = fma2(dl0, g0, qacc0);
            qacc1 = fma2(dl1, g1, qacc1);
            dacc0 = add2(dacc0, dl0);
            dacc1 = add2(dacc1, dl1);
        }
        __syncthreads();
    }

    // horizontal: sum pair, then reduce across the 4 lanes sharing a row
    float2 q0p = unpack2(qacc0), q1p = unpack2(qacc1);
    float2 d0p = unpack2(dacc0), d1p = unpack2(dacc1);
    float q0 = q0p.x + q0p.y, q1 = q1p.x + q1p.y;
    float d0 = d0p.x + d0p.y, d1 = d1p.x + d1p.y;
#pragma unroll
    for (int off = 1; off < 4; off <<= 1) {
        q0 += __shfl_xor_sync(0xFFFFFFFF, q0, off);
        q1 += __shfl_xor_sync(0xFFFFFFFF, q1, off);
        d0 += __shfl_xor_sync(0xFFFFFFFF, d0, off);
        d1 += __shfl_xor_sync(0xFFFFFFFF, d1, off);
    }
    if ((lane & 3) == 0) {
        int base = (br * Bn + b) * Cn;
        int cA = c0 + row, cB = c0 + row + 8;
        if (cA < Cn) { g_q[base + cA] = q0; g_Ds[base + cA] = d0; }
        if (cB < Cn) { g_q[base + cB] = q1; g_Ds[base + cB] = d1; }
    }
}

// ---------------- y_hat + loss ----------------
__global__ __launch_bounds__(256) void yhat_kernel(const float* __restrict__ y,
                                                   const float* __restrict__ Wf,
                                                   const float* __restrict__ bf,
                                                   float* __restrict__ out) {
    int i = blockIdx.x * 256 + threadIdx.x;
    float lt = 0.f;
    if (i < Bn * Cn) {
        int b = i / Cn, c = i - b * Cn;
        float yh = bf[c];
#pragma unroll
        for (int br = 0; br < 4; br++) {
            const float* wfp = Wf + (size_t)c * (4 * Fn) + br * Fn;
            const float* hsv = g_hsum + (br * Bn + b) * Fn;
            float dot = 0.f;
#pragma unroll
            for (int f = 0; f < Fn; f++) dot = fmaf(wfp[f], hsv[f], dot);
            int idx = (br * Bn + b) * Cn + c;
            yh += (dot + g_q[idx]) / (2048.f + g_Ds[idx]);
        }
        out[i] = yh;
        lt = fmaxf(yh, 0.f) - yh * y[i] + log1pf(expf(-fabsf(yh)));
    }
    __shared__ float red[256];
    red[threadIdx.x] = lt;
    __syncthreads();
    for (int o = 128; o > 0; o >>= 1) {
        if (threadIdx.x < o) red[threadIdx.x] += red[threadIdx.x + o];
        __syncthreads();
    }
    if (threadIdx.x == 0) g_lsum[blockIdx.x] = red[0];
}

__global__ void loss_kernel(float* __restrict__ out, int pos, int nblocks) {
    __shared__ float red[256];
    float s = 0.f;
    for (int i = threadIdx.x; i < nblocks; i += 256) s += g_lsum[i];
    red[threadIdx.x] = s;
    __syncthreads();
    for (int o = 128; o > 0; o >>= 1) {
        if (threadIdx.x < o) red[threadIdx.x] += red[threadIdx.x + o];
        __syncthreads();
    }
    if (threadIdx.x == 0) out[pos] = red[0] / (float)(Bn * Cn);
}

// ---------------- launch ----------------
extern "C" void kernel_launch(void* const* d_in, const int* in_sizes, int n_in,
                              void* d_out, int out_size) {
    const int* x = (const int*)d_in[0];
    const float* y = (const float*)d_in[1];
    const float* embed = (const float*)d_in[2];
    const float* w3 = (const float*)d_in[3];
    const float* b3 = (const float*)d_in[4];
    const float* w5 = (const float*)d_in[5];
    const float* b5 = (const float*)d_in[6];
    const float* w7 = (const float*)d_in[7];
    const float* b7 = (const float*)d_in[8];
    const float* w9 = (const float*)d_in[9];
    const float* b9 = (const float*)d_in[10];
    const float* U3 = (const float*)d_in[11];
    const float* U5 = (const float*)d_in[12];
    const float* U7 = (const float*)d_in[13];
    const float* U9 = (const float*)d_in[14];
    const float* Wf = (const float*)d_in[15];
    const float* bf = (const float*)d_in[16];
    float* out = (float*)d_out;

    const int CONV_SMEM = (72 * 104 + 20 * 9 * 68) * 4;
    cudaFuncSetAttribute(conv_kernel, cudaFuncAttributeMaxDynamicSharedMemorySize, CONV_SMEM);

    prep_kernel<<<(4 * Cn * Fn + 255) / 256, 256>>>(U3, U5, U7, U9, Wf);
    conv_kernel<<<dim3(Sn / 64, Bn, 4), 256, CONV_SMEM>>>(x, embed, w3, b3, w5, b5, w7, b7, w9, b9);
    attn_kernel<<<dim3(NCT, 4, Bn), 256>>>();

    const int nblocks = (Bn * Cn + 255) / 256;
    yhat_kernel<<<nblocks, 256>>>(y, Wf, bf, out);
    if (out_size > Bn * Cn) loss_kernel<<<1, 256>>>(out, out_size - 1, nblocks);
}